// round 3
// baseline (speedup 1.0000x reference)
#include <cuda_runtime.h>
#include <cuda_fp16.h>
#include <math.h>

#define N_NODES 4096
#define FIN     128
#define NHEAD   8
#define FOUT    64
#define HF      512                 // NHEAD*FOUT
#define HF2     256                 // HF/2 half2 per row
#define OUT_ELEMS (N_NODES*HF)      // 2097152
#define ADJ_ELEMS (N_NODES*N_NODES) // 16777216
#define MAXDEG  512

// Scratch (allocation-free rule: __device__ globals)
__device__ float  g_proj[N_NODES*HF];    // [n][h*64+d] fp32 (score path)
__device__ __half2 g_projh2[N_NODES*HF2]; // fp16 copy, [n][pair] (gather path)
__device__ float  g_skip[N_NODES*HF];
__device__ float  g_ssrc[NHEAD*N_NODES];
__device__ float  g_stgt[NHEAD*N_NODES];

// ---------------------------------------------------------------------------
// Kernel 1: fused projection GEMM.  C[4096,1024] = x[4096,128] @ [Wp;Ws]^T
// 128x128 block tile, BK=16, 256 threads, 8x8 micro-tile.
// proj tiles additionally emit an fp16 copy for the attention gather.
// ---------------------------------------------------------------------------
#define BM 128
#define BN 128
#define BK 16

__global__ __launch_bounds__(256, 2) void gemm_kernel(
    const float* __restrict__ x,
    const float* __restrict__ Wp,
    const float* __restrict__ Ws)
{
    __shared__ float xs[BK][BM + 4];
    __shared__ float ws[BK][BN + 4];

    const int bm = blockIdx.y * BM;
    const int bo = blockIdx.x * BN;          // tile fully in Wp or Ws
    const int t  = threadIdx.x;
    const int tx = t & 15;
    const int ty = t >> 4;

    float acc[8][8];
#pragma unroll
    for (int i = 0; i < 8; i++)
#pragma unroll
        for (int j = 0; j < 8; j++) acc[i][j] = 0.f;

    const float* Wb = (bo < HF) ? (Wp + (size_t)bo * FIN)
                                : (Ws + (size_t)(bo - HF) * FIN);

    for (int kt = 0; kt < FIN; kt += BK) {
#pragma unroll
        for (int v = 0; v < 2; v++) {
            int idx = t + v * 256;
            int row = idx >> 2, f4 = idx & 3;
            float4 xv = *reinterpret_cast<const float4*>(
                x + (size_t)(bm + row) * FIN + kt + f4 * 4);
            xs[f4*4+0][row] = xv.x; xs[f4*4+1][row] = xv.y;
            xs[f4*4+2][row] = xv.z; xs[f4*4+3][row] = xv.w;
        }
#pragma unroll
        for (int v = 0; v < 2; v++) {
            int idx = t + v * 256;
            int o = idx >> 2, f4 = idx & 3;
            float4 wv = *reinterpret_cast<const float4*>(
                Wb + (size_t)o * FIN + kt + f4 * 4);
            ws[f4*4+0][o] = wv.x; ws[f4*4+1][o] = wv.y;
            ws[f4*4+2][o] = wv.z; ws[f4*4+3][o] = wv.w;
        }
        __syncthreads();
#pragma unroll
        for (int k = 0; k < BK; k++) {
            float a[8], b[8];
            *reinterpret_cast<float4*>(a)     = *reinterpret_cast<const float4*>(&xs[k][ty*8]);
            *reinterpret_cast<float4*>(a + 4) = *reinterpret_cast<const float4*>(&xs[k][ty*8+4]);
            *reinterpret_cast<float4*>(b)     = *reinterpret_cast<const float4*>(&ws[k][tx*8]);
            *reinterpret_cast<float4*>(b + 4) = *reinterpret_cast<const float4*>(&ws[k][tx*8+4]);
#pragma unroll
            for (int i = 0; i < 8; i++)
#pragma unroll
                for (int j = 0; j < 8; j++) acc[i][j] = fmaf(a[i], b[j], acc[i][j]);
        }
        __syncthreads();
    }

    if (bo < HF) {
#pragma unroll
        for (int i = 0; i < 8; i++) {
            int m = bm + ty*8 + i;
            float* drow = g_proj + (size_t)m * HF + bo + tx*8;
            *reinterpret_cast<float4*>(drow)     = make_float4(acc[i][0], acc[i][1], acc[i][2], acc[i][3]);
            *reinterpret_cast<float4*>(drow + 4) = make_float4(acc[i][4], acc[i][5], acc[i][6], acc[i][7]);
            __half2* hrow = g_projh2 + (size_t)m * HF2 + (bo >> 1) + tx*4;
            hrow[0] = __floats2half2_rn(acc[i][0], acc[i][1]);
            hrow[1] = __floats2half2_rn(acc[i][2], acc[i][3]);
            hrow[2] = __floats2half2_rn(acc[i][4], acc[i][5]);
            hrow[3] = __floats2half2_rn(acc[i][6], acc[i][7]);
        }
    } else {
        const int cb = bo - HF;
#pragma unroll
        for (int i = 0; i < 8; i++) {
            int m = bm + ty*8 + i;
            float* drow = g_skip + (size_t)m * HF + cb + tx*8;
            *reinterpret_cast<float4*>(drow)     = make_float4(acc[i][0], acc[i][1], acc[i][2], acc[i][3]);
            *reinterpret_cast<float4*>(drow + 4) = make_float4(acc[i][4], acc[i][5], acc[i][6], acc[i][7]);
        }
    }
}

// ---------------------------------------------------------------------------
// Kernel 2: per-node attention scores  s_src[h][n], s_tgt[h][n]
// ---------------------------------------------------------------------------
__global__ __launch_bounds__(256) void score_kernel(
    const float* __restrict__ a_src,
    const float* __restrict__ a_tgt)
{
    int gw   = (blockIdx.x * 256 + threadIdx.x) >> 5;
    int lane = threadIdx.x & 31;
    if (gw >= N_NODES) return;
    const float* pr = g_proj + (size_t)gw * HF;
#pragma unroll
    for (int h = 0; h < NHEAD; h++) {
        float p0 = pr[h*64 + lane];
        float p1 = pr[h*64 + 32 + lane];
        float ss = p0 * a_src[h*64 + lane] + p1 * a_src[h*64 + 32 + lane];
        float st = p0 * a_tgt[h*64 + lane] + p1 * a_tgt[h*64 + 32 + lane];
#pragma unroll
        for (int off = 16; off; off >>= 1) {
            ss += __shfl_xor_sync(0xffffffffu, ss, off);
            st += __shfl_xor_sync(0xffffffffu, st, off);
        }
        if (lane == 0) {
            g_ssrc[h*N_NODES + gw] = ss;
            g_stgt[h*N_NODES + gw] = st;
        }
    }
}

// ---------------------------------------------------------------------------
// Kernel 3: sparse attention. One block per row i.
//   Phase 1: adj scan + copy, ordered neighbor compaction.
//   Phase 2: warp-per-head softmax (warp w owns head w).
//   Phase 3: fp16 half2 gather-accumulate; thread t owns dims {2t, 2t+1}
//            (head = warp id), fp32 accumulation; skip+bias+ELU epilogue.
// ---------------------------------------------------------------------------
__global__ __launch_bounds__(256) void attn_kernel(
    const float* __restrict__ adj,
    const float* __restrict__ bias,
    float* __restrict__ out,
    float* __restrict__ out_adj,
    int write_adj)
{
    __shared__ int   nbr[MAXDEG];
    __shared__ float wsm[NHEAD * MAXDEG];
    __shared__ int   warpsum[8];
    __shared__ float ssum[NHEAD];

    const int i    = blockIdx.x;
    const int t    = threadIdx.x;
    const int lane = t & 31;
    const int w    = t >> 5;

    const float4* arow = reinterpret_cast<const float4*>(adj + (size_t)i * N_NODES);
    float4*       orow = reinterpret_cast<float4*>(out_adj + (size_t)i * N_NODES);

    // ---- Phase 1: ordered neighbor compaction -----------------------------
    int cnt = 0;
#pragma unroll
    for (int it = 0; it < 4; it++) {
        int idx4 = it * 256 + t;
        float4 a = arow[idx4];
        if (write_adj) orow[idx4] = a;
        int p0 = a.x > -0.5f;
        int p1 = a.y > -0.5f;
        int p2 = a.z > -0.5f;
        int p3 = a.w > -0.5f;
        int c = p0 + p1 + p2 + p3;
        int v = c;
#pragma unroll
        for (int off = 1; off < 32; off <<= 1) {
            int n = __shfl_up_sync(0xffffffffu, v, off);
            if (lane >= off) v += n;
        }
        if (lane == 31) warpsum[w] = v;
        __syncthreads();
        int wbase = 0, tot = 0;
#pragma unroll
        for (int ww = 0; ww < 8; ww++) {
            int s = warpsum[ww];
            if (ww < w) wbase += s;
            tot += s;
        }
        int pos = cnt + wbase + (v - c);   // exclusive prefix, j-ordered
        int j = idx4 * 4;
        if (p0 && pos < MAXDEG) nbr[pos++] = j;
        if (p1 && pos < MAXDEG) nbr[pos++] = j + 1;
        if (p2 && pos < MAXDEG) nbr[pos++] = j + 2;
        if (p3 && pos < MAXDEG) nbr[pos++] = j + 3;
        cnt += tot;
        __syncthreads();
    }
    const int deg = min(cnt, MAXDEG);

    // ---- Phase 2: warp-per-head softmax over neighbors --------------------
    {
        const int h = w;
        const float ssrc = g_ssrc[h*N_NODES + i];
        const float* stgt = g_stgt + h*N_NODES;
        float* wrow = wsm + h * MAXDEG;

        float lmax = -1e30f;
        for (int k = lane; k < deg; k += 32) {
            float xv = ssrc + stgt[nbr[k]];
            float l  = xv >= 0.f ? xv : 0.2f * xv;    // leaky_relu(0.2)
            wrow[k] = l;
            lmax = fmaxf(lmax, l);
        }
#pragma unroll
        for (int off = 16; off; off >>= 1)
            lmax = fmaxf(lmax, __shfl_xor_sync(0xffffffffu, lmax, off));

        float lsum = 0.f;
        for (int k = lane; k < deg; k += 32) {
            float e = expf(wrow[k] - lmax);
            wrow[k] = e;
            lsum += e;
        }
#pragma unroll
        for (int off = 16; off; off >>= 1)
            lsum += __shfl_xor_sync(0xffffffffu, lsum, off);
        if (lane == 0) ssum[h] = lsum;
    }
    __syncthreads();

    // ---- Phase 3: fp16 gather-accumulate ----------------------------------
    // thread t -> dims {2t, 2t+1}; head = t/32 = warp id w.
    const float* wv = wsm + w * MAXDEG;     // warp-uniform broadcast reads
    float ax = 0.f, ay = 0.f;
    int k = 0;
    for (; k + 4 <= deg; k += 4) {
        int n0 = nbr[k], n1 = nbr[k+1], n2 = nbr[k+2], n3 = nbr[k+3];
        __half2 h0 = g_projh2[(size_t)n0 * HF2 + t];
        __half2 h1 = g_projh2[(size_t)n1 * HF2 + t];
        __half2 h2 = g_projh2[(size_t)n2 * HF2 + t];
        __half2 h3 = g_projh2[(size_t)n3 * HF2 + t];
        float w0 = wv[k], w1 = wv[k+1], w2 = wv[k+2], w3 = wv[k+3];
        float2 f0 = __half22float2(h0);
        float2 f1 = __half22float2(h1);
        float2 f2 = __half22float2(h2);
        float2 f3 = __half22float2(h3);
        ax = fmaf(w0, f0.x, ax); ay = fmaf(w0, f0.y, ay);
        ax = fmaf(w1, f1.x, ax); ay = fmaf(w1, f1.y, ay);
        ax = fmaf(w2, f2.x, ax); ay = fmaf(w2, f2.y, ay);
        ax = fmaf(w3, f3.x, ax); ay = fmaf(w3, f3.y, ay);
    }
    for (; k < deg; k++) {
        float2 f = __half22float2(g_projh2[(size_t)nbr[k] * HF2 + t]);
        float wk = wv[k];
        ax = fmaf(wk, f.x, ax); ay = fmaf(wk, f.y, ay);
    }

    const float inv = 1.f / ssum[w];
    float2 sk = *reinterpret_cast<const float2*>(g_skip + (size_t)i*HF + 2*t);
    float2 bz = *reinterpret_cast<const float2*>(bias + 2*t);
    float v0 = ax * inv + sk.x + bz.x;
    float v1 = ay * inv + sk.y + bz.y;
    float2 o;
    o.x = v0 > 0.f ? v0 : expm1f(v0);       // ELU(alpha=1)
    o.y = v1 > 0.f ? v1 : expm1f(v1);
    *reinterpret_cast<float2*>(out + (size_t)i*HF + 2*t) = o;
}

// ---------------------------------------------------------------------------
extern "C" void kernel_launch(void* const* d_in, const int* in_sizes, int n_in,
                              void* d_out, int out_size)
{
    const float* x     = (const float*)d_in[0];
    const float* adj   = (const float*)d_in[1];
    const float* Wp    = (const float*)d_in[2];
    const float* a_src = (const float*)d_in[3];
    const float* a_tgt = (const float*)d_in[4];
    const float* Ws    = (const float*)d_in[5];
    const float* bias  = (const float*)d_in[6];
    float* out = (float*)d_out;

    int write_adj = (out_size >= OUT_ELEMS + ADJ_ELEMS) ? 1 : 0;
    float* out_adj = write_adj ? (out + OUT_ELEMS) : out;

    dim3 ggrid(1024 / BN, N_NODES / BM);          // (8, 32)
    gemm_kernel<<<ggrid, 256>>>(x, Wp, Ws);
    score_kernel<<<N_NODES / 8, 256>>>(a_src, a_tgt);
    attn_kernel<<<N_NODES, 256>>>(adj, bias, out, out_adj, write_adj);
}

// round 4
// speedup vs baseline: 1.1323x; 1.1323x over previous
#include <cuda_runtime.h>
#include <math.h>

#define N_NODES 4096
#define FIN     128
#define NHEAD   8
#define FOUT    64
#define HF      512                 // NHEAD*FOUT
#define OUT_ELEMS (N_NODES*HF)      // 2097152
#define ADJ_ELEMS (N_NODES*N_NODES) // 16777216
#define MAXDEG  512

// Scratch (allocation-free rule: __device__ globals)
__device__ float g_proj[N_NODES*HF];   // [n][h*64+d]
__device__ float g_skip[N_NODES*HF];
__device__ float g_ssrc[NHEAD*N_NODES];
__device__ float g_stgt[NHEAD*N_NODES];
__device__ int   g_deg[N_NODES];
__device__ int   g_nbr[(size_t)N_NODES*MAXDEG];

// ---------------------------------------------------------------------------
// Kernel 0: adj scan + copy + CSR build. One block per row.
// All loads hoisted (single DRAM latency), one block-scan (2 barriers).
// Thread t owns columns [16t, 16t+16) -> global j-ordering preserved.
// ---------------------------------------------------------------------------
__global__ __launch_bounds__(256) void scan_copy_kernel(
    const float* __restrict__ adj,
    float* __restrict__ out_adj,
    int write_adj)
{
    __shared__ int warpsum[8];
    const int i    = blockIdx.x;
    const int t    = threadIdx.x;
    const int lane = t & 31;
    const int w    = t >> 5;

    const float4* arow = reinterpret_cast<const float4*>(adj + (size_t)i * N_NODES);
    float4*       orow = reinterpret_cast<float4*>(out_adj + (size_t)i * N_NODES);

    float4 a[4];
#pragma unroll
    for (int v = 0; v < 4; v++) a[v] = arow[4*t + v];
    if (write_adj) {
#pragma unroll
        for (int v = 0; v < 4; v++) orow[4*t + v] = a[v];
    }

    unsigned flags = 0;
#pragma unroll
    for (int v = 0; v < 4; v++) {
        flags |= (a[v].x > -0.5f ? 1u : 0u) << (4*v + 0);
        flags |= (a[v].y > -0.5f ? 1u : 0u) << (4*v + 1);
        flags |= (a[v].z > -0.5f ? 1u : 0u) << (4*v + 2);
        flags |= (a[v].w > -0.5f ? 1u : 0u) << (4*v + 3);
    }
    int c = __popc(flags);

    int incl = c;
#pragma unroll
    for (int off = 1; off < 32; off <<= 1) {
        int n = __shfl_up_sync(0xffffffffu, incl, off);
        if (lane >= off) incl += n;
    }
    if (lane == 31) warpsum[w] = incl;
    __syncthreads();
    int wbase = 0, tot = 0;
#pragma unroll
    for (int ww = 0; ww < 8; ww++) {
        int s = warpsum[ww];
        if (ww < w) wbase += s;
        tot += s;
    }

    int pos = wbase + incl - c;        // exclusive prefix, column-ordered
    int base = 16 * t;
    int* nrow = g_nbr + (size_t)i * MAXDEG;
#pragma unroll
    for (int b = 0; b < 16; b++) {
        if ((flags >> b) & 1u) {
            if (pos < MAXDEG) nrow[pos] = base + b;
            pos++;
        }
    }
    if (t == 0) g_deg[i] = min(tot, MAXDEG);
}

// ---------------------------------------------------------------------------
// Kernel 1: fused projection GEMM.  C[4096,1024] = x[4096,128] @ [Wp;Ws]^T
// 128x128 block tile, BK=16, 256 threads, 8x8 micro-tile.
// ---------------------------------------------------------------------------
#define BM 128
#define BN 128
#define BK 16

__global__ __launch_bounds__(256, 2) void gemm_kernel(
    const float* __restrict__ x,
    const float* __restrict__ Wp,
    const float* __restrict__ Ws)
{
    __shared__ float xs[BK][BM + 4];
    __shared__ float ws[BK][BN + 4];

    const int bm = blockIdx.y * BM;
    const int bo = blockIdx.x * BN;
    const int t  = threadIdx.x;
    const int tx = t & 15;
    const int ty = t >> 4;

    float acc[8][8];
#pragma unroll
    for (int i = 0; i < 8; i++)
#pragma unroll
        for (int j = 0; j < 8; j++) acc[i][j] = 0.f;

    const float* Wb = (bo < HF) ? (Wp + (size_t)bo * FIN)
                                : (Ws + (size_t)(bo - HF) * FIN);

    for (int kt = 0; kt < FIN; kt += BK) {
#pragma unroll
        for (int v = 0; v < 2; v++) {
            int idx = t + v * 256;
            int row = idx >> 2, f4 = idx & 3;
            float4 xv = *reinterpret_cast<const float4*>(
                x + (size_t)(bm + row) * FIN + kt + f4 * 4);
            xs[f4*4+0][row] = xv.x; xs[f4*4+1][row] = xv.y;
            xs[f4*4+2][row] = xv.z; xs[f4*4+3][row] = xv.w;
        }
#pragma unroll
        for (int v = 0; v < 2; v++) {
            int idx = t + v * 256;
            int o = idx >> 2, f4 = idx & 3;
            float4 wv = *reinterpret_cast<const float4*>(
                Wb + (size_t)o * FIN + kt + f4 * 4);
            ws[f4*4+0][o] = wv.x; ws[f4*4+1][o] = wv.y;
            ws[f4*4+2][o] = wv.z; ws[f4*4+3][o] = wv.w;
        }
        __syncthreads();
#pragma unroll
        for (int k = 0; k < BK; k++) {
            float a[8], b[8];
            *reinterpret_cast<float4*>(a)     = *reinterpret_cast<const float4*>(&xs[k][ty*8]);
            *reinterpret_cast<float4*>(a + 4) = *reinterpret_cast<const float4*>(&xs[k][ty*8+4]);
            *reinterpret_cast<float4*>(b)     = *reinterpret_cast<const float4*>(&ws[k][tx*8]);
            *reinterpret_cast<float4*>(b + 4) = *reinterpret_cast<const float4*>(&ws[k][tx*8+4]);
#pragma unroll
            for (int i = 0; i < 8; i++)
#pragma unroll
                for (int j = 0; j < 8; j++) acc[i][j] = fmaf(a[i], b[j], acc[i][j]);
        }
        __syncthreads();
    }

    float* dst = (bo < HF) ? g_proj : g_skip;
    const int cb = (bo < HF) ? bo : (bo - HF);
#pragma unroll
    for (int i = 0; i < 8; i++) {
        int m = bm + ty*8 + i;
        float* drow = dst + (size_t)m * HF + cb + tx*8;
        *reinterpret_cast<float4*>(drow)     = make_float4(acc[i][0], acc[i][1], acc[i][2], acc[i][3]);
        *reinterpret_cast<float4*>(drow + 4) = make_float4(acc[i][4], acc[i][5], acc[i][6], acc[i][7]);
    }
}

// ---------------------------------------------------------------------------
// Kernel 2: per-node attention scores  s_src[h][n], s_tgt[h][n]
// ---------------------------------------------------------------------------
__global__ __launch_bounds__(256) void score_kernel(
    const float* __restrict__ a_src,
    const float* __restrict__ a_tgt)
{
    int gw   = (blockIdx.x * 256 + threadIdx.x) >> 5;
    int lane = threadIdx.x & 31;
    if (gw >= N_NODES) return;
    const float* pr = g_proj + (size_t)gw * HF;
#pragma unroll
    for (int h = 0; h < NHEAD; h++) {
        float p0 = pr[h*64 + lane];
        float p1 = pr[h*64 + 32 + lane];
        float ss = p0 * a_src[h*64 + lane] + p1 * a_src[h*64 + 32 + lane];
        float st = p0 * a_tgt[h*64 + lane] + p1 * a_tgt[h*64 + 32 + lane];
#pragma unroll
        for (int off = 16; off; off >>= 1) {
            ss += __shfl_xor_sync(0xffffffffu, ss, off);
            st += __shfl_xor_sync(0xffffffffu, st, off);
        }
        if (lane == 0) {
            g_ssrc[h*N_NODES + gw] = ss;
            g_stgt[h*N_NODES + gw] = st;
        }
    }
}

// ---------------------------------------------------------------------------
// Kernel 3: sparse attention (no adj access). One block per row i.
//   Load CSR nbr list -> warp-per-head softmax -> fp32 gather-accumulate.
// ---------------------------------------------------------------------------
__global__ __launch_bounds__(256) void attn_kernel(
    const float* __restrict__ bias,
    float* __restrict__ out)
{
    __shared__ int   nbr[MAXDEG];
    __shared__ float wsm[NHEAD * MAXDEG];
    __shared__ float ssum[NHEAD];

    const int i    = blockIdx.x;
    const int t    = threadIdx.x;
    const int lane = t & 31;
    const int w    = t >> 5;

    const int deg = g_deg[i];
    const int* nrow = g_nbr + (size_t)i * MAXDEG;
    for (int k = t; k < deg; k += 256) nbr[k] = nrow[k];
    __syncthreads();

    // ---- warp-per-head softmax over neighbors -----------------------------
    {
        const int h = w;
        const float ssrc = g_ssrc[h*N_NODES + i];
        const float* stgt = g_stgt + h*N_NODES;
        float* wrow = wsm + h * MAXDEG;

        float lmax = -1e30f;
        for (int k = lane; k < deg; k += 32) {
            float xv = ssrc + stgt[nbr[k]];
            float l  = xv >= 0.f ? xv : 0.2f * xv;    // leaky_relu(0.2)
            wrow[k] = l;
            lmax = fmaxf(lmax, l);
        }
#pragma unroll
        for (int off = 16; off; off >>= 1)
            lmax = fmaxf(lmax, __shfl_xor_sync(0xffffffffu, lmax, off));

        float lsum = 0.f;
        for (int k = lane; k < deg; k += 32) {
            float e = expf(wrow[k] - lmax);
            wrow[k] = e;
            lsum += e;
        }
#pragma unroll
        for (int off = 16; off; off >>= 1)
            lsum += __shfl_xor_sync(0xffffffffu, lsum, off);
        if (lane == 0) ssum[h] = lsum;
    }
    __syncthreads();

    // ---- gather-accumulate (each proj row serves all 8 heads) -------------
    const int p1 = t, p2 = t + 256;
    const float* w1 = wsm + (p1 >> 6) * MAXDEG;
    const float* w2 = wsm + (p2 >> 6) * MAXDEG;
    float acc1 = 0.f, acc2 = 0.f;
    int k = 0;
    for (; k + 4 <= deg; k += 4) {
        int n0 = nbr[k], n1 = nbr[k+1], n2 = nbr[k+2], n3 = nbr[k+3];
        const float* r0 = g_proj + (size_t)n0 * HF;
        const float* r1 = g_proj + (size_t)n1 * HF;
        const float* r2 = g_proj + (size_t)n2 * HF;
        const float* r3 = g_proj + (size_t)n3 * HF;
        float a0 = r0[p1], a1 = r1[p1], a2 = r2[p1], a3 = r3[p1];
        float b0 = r0[p2], b1 = r1[p2], b2 = r2[p2], b3 = r3[p2];
        acc1 += w1[k]   * a0;
        acc1 += w1[k+1] * a1;
        acc1 += w1[k+2] * a2;
        acc1 += w1[k+3] * a3;
        acc2 += w2[k]   * b0;
        acc2 += w2[k+1] * b1;
        acc2 += w2[k+2] * b2;
        acc2 += w2[k+3] * b3;
    }
    for (; k < deg; k++) {
        const float* r = g_proj + (size_t)nbr[k] * HF;
        acc1 += w1[k] * r[p1];
        acc2 += w2[k] * r[p2];
    }

    float v1 = acc1 / ssum[p1 >> 6] + g_skip[(size_t)i*HF + p1] + bias[p1];
    float v2 = acc2 / ssum[p2 >> 6] + g_skip[(size_t)i*HF + p2] + bias[p2];
    out[(size_t)i*HF + p1] = v1 > 0.f ? v1 : expm1f(v1);   // ELU(alpha=1)
    out[(size_t)i*HF + p2] = v2 > 0.f ? v2 : expm1f(v2);
}

// ---------------------------------------------------------------------------
extern "C" void kernel_launch(void* const* d_in, const int* in_sizes, int n_in,
                              void* d_out, int out_size)
{
    const float* x     = (const float*)d_in[0];
    const float* adj   = (const float*)d_in[1];
    const float* Wp    = (const float*)d_in[2];
    const float* a_src = (const float*)d_in[3];
    const float* a_tgt = (const float*)d_in[4];
    const float* Ws    = (const float*)d_in[5];
    const float* bias  = (const float*)d_in[6];
    float* out = (float*)d_out;

    int write_adj = (out_size >= OUT_ELEMS + ADJ_ELEMS) ? 1 : 0;
    float* out_adj = write_adj ? (out + OUT_ELEMS) : out;

    scan_copy_kernel<<<N_NODES, 256>>>(adj, out_adj, write_adj);
    dim3 ggrid(1024 / BN, N_NODES / BM);          // (8, 32)
    gemm_kernel<<<ggrid, 256>>>(x, Wp, Ws);
    score_kernel<<<N_NODES / 8, 256>>>(a_src, a_tgt);
    attn_kernel<<<N_NODES, 256>>>(bias, out);
}

// round 5
// speedup vs baseline: 1.1687x; 1.0321x over previous
#include <cuda_runtime.h>
#include <math.h>

#define N_NODES 4096
#define FIN     128
#define NHEAD   8
#define FOUT    64
#define HF      512                 // NHEAD*FOUT
#define OUT_ELEMS (N_NODES*HF)      // 2097152
#define ADJ_ELEMS (N_NODES*N_NODES) // 16777216
#define MAXDEG  512

// Scratch (allocation-free rule: __device__ globals)
__device__ float g_proj[N_NODES*HF];   // [n][h*64+d]
__device__ float g_skip[N_NODES*HF];
__device__ float g_ssrc[NHEAD*N_NODES];
__device__ float g_stgt[NHEAD*N_NODES];
__device__ int   g_deg[N_NODES];
__device__ int   g_nbr[(size_t)N_NODES*MAXDEG];

// ---------------------------------------------------------------------------
// Kernel 0: adj scan + copy + CSR build. One block per row.
// ---------------------------------------------------------------------------
__global__ __launch_bounds__(256) void scan_copy_kernel(
    const float* __restrict__ adj,
    float* __restrict__ out_adj,
    int write_adj)
{
    __shared__ int warpsum[8];
    const int i    = blockIdx.x;
    const int t    = threadIdx.x;
    const int lane = t & 31;
    const int w    = t >> 5;

    const float4* arow = reinterpret_cast<const float4*>(adj + (size_t)i * N_NODES);
    float4*       orow = reinterpret_cast<float4*>(out_adj + (size_t)i * N_NODES);

    float4 a[4];
#pragma unroll
    for (int v = 0; v < 4; v++) a[v] = arow[4*t + v];
    if (write_adj) {
#pragma unroll
        for (int v = 0; v < 4; v++) orow[4*t + v] = a[v];
    }

    unsigned flags = 0;
#pragma unroll
    for (int v = 0; v < 4; v++) {
        flags |= (a[v].x > -0.5f ? 1u : 0u) << (4*v + 0);
        flags |= (a[v].y > -0.5f ? 1u : 0u) << (4*v + 1);
        flags |= (a[v].z > -0.5f ? 1u : 0u) << (4*v + 2);
        flags |= (a[v].w > -0.5f ? 1u : 0u) << (4*v + 3);
    }
    int c = __popc(flags);

    int incl = c;
#pragma unroll
    for (int off = 1; off < 32; off <<= 1) {
        int n = __shfl_up_sync(0xffffffffu, incl, off);
        if (lane >= off) incl += n;
    }
    if (lane == 31) warpsum[w] = incl;
    __syncthreads();
    int wbase = 0, tot = 0;
#pragma unroll
    for (int ww = 0; ww < 8; ww++) {
        int s = warpsum[ww];
        if (ww < w) wbase += s;
        tot += s;
    }

    int pos = wbase + incl - c;        // exclusive prefix, column-ordered
    int base = 16 * t;
    int* nrow = g_nbr + (size_t)i * MAXDEG;
#pragma unroll
    for (int b = 0; b < 16; b++) {
        if ((flags >> b) & 1u) {
            if (pos < MAXDEG) nrow[pos] = base + b;
            pos++;
        }
    }
    if (t == 0) g_deg[i] = min(tot, MAXDEG);
}

// ---------------------------------------------------------------------------
// Kernel 1: fused projection GEMM.  C[4096,1024] = x[4096,128] @ [Wp;Ws]^T
// ---------------------------------------------------------------------------
#define BM 128
#define BN 128
#define BK 16

__global__ __launch_bounds__(256, 2) void gemm_kernel(
    const float* __restrict__ x,
    const float* __restrict__ Wp,
    const float* __restrict__ Ws)
{
    __shared__ float xs[BK][BM + 4];
    __shared__ float ws[BK][BN + 4];

    const int bm = blockIdx.y * BM;
    const int bo = blockIdx.x * BN;
    const int t  = threadIdx.x;
    const int tx = t & 15;
    const int ty = t >> 4;

    float acc[8][8];
#pragma unroll
    for (int i = 0; i < 8; i++)
#pragma unroll
        for (int j = 0; j < 8; j++) acc[i][j] = 0.f;

    const float* Wb = (bo < HF) ? (Wp + (size_t)bo * FIN)
                                : (Ws + (size_t)(bo - HF) * FIN);

    for (int kt = 0; kt < FIN; kt += BK) {
#pragma unroll
        for (int v = 0; v < 2; v++) {
            int idx = t + v * 256;
            int row = idx >> 2, f4 = idx & 3;
            float4 xv = *reinterpret_cast<const float4*>(
                x + (size_t)(bm + row) * FIN + kt + f4 * 4);
            xs[f4*4+0][row] = xv.x; xs[f4*4+1][row] = xv.y;
            xs[f4*4+2][row] = xv.z; xs[f4*4+3][row] = xv.w;
        }
#pragma unroll
        for (int v = 0; v < 2; v++) {
            int idx = t + v * 256;
            int o = idx >> 2, f4 = idx & 3;
            float4 wv = *reinterpret_cast<const float4*>(
                Wb + (size_t)o * FIN + kt + f4 * 4);
            ws[f4*4+0][o] = wv.x; ws[f4*4+1][o] = wv.y;
            ws[f4*4+2][o] = wv.z; ws[f4*4+3][o] = wv.w;
        }
        __syncthreads();
#pragma unroll
        for (int k = 0; k < BK; k++) {
            float a[8], b[8];
            *reinterpret_cast<float4*>(a)     = *reinterpret_cast<const float4*>(&xs[k][ty*8]);
            *reinterpret_cast<float4*>(a + 4) = *reinterpret_cast<const float4*>(&xs[k][ty*8+4]);
            *reinterpret_cast<float4*>(b)     = *reinterpret_cast<const float4*>(&ws[k][tx*8]);
            *reinterpret_cast<float4*>(b + 4) = *reinterpret_cast<const float4*>(&ws[k][tx*8+4]);
#pragma unroll
            for (int i = 0; i < 8; i++)
#pragma unroll
                for (int j = 0; j < 8; j++) acc[i][j] = fmaf(a[i], b[j], acc[i][j]);
        }
        __syncthreads();
    }

    float* dst = (bo < HF) ? g_proj : g_skip;
    const int cb = (bo < HF) ? bo : (bo - HF);
#pragma unroll
    for (int i = 0; i < 8; i++) {
        int m = bm + ty*8 + i;
        float* drow = dst + (size_t)m * HF + cb + tx*8;
        *reinterpret_cast<float4*>(drow)     = make_float4(acc[i][0], acc[i][1], acc[i][2], acc[i][3]);
        *reinterpret_cast<float4*>(drow + 4) = make_float4(acc[i][4], acc[i][5], acc[i][6], acc[i][7]);
    }
}

// ---------------------------------------------------------------------------
// Kernel 2: per-node attention scores  s_src[h][n], s_tgt[h][n]
// ---------------------------------------------------------------------------
__global__ __launch_bounds__(256) void score_kernel(
    const float* __restrict__ a_src,
    const float* __restrict__ a_tgt)
{
    int gw   = (blockIdx.x * 256 + threadIdx.x) >> 5;
    int lane = threadIdx.x & 31;
    if (gw >= N_NODES) return;
    const float* pr = g_proj + (size_t)gw * HF;
#pragma unroll
    for (int h = 0; h < NHEAD; h++) {
        float p0 = pr[h*64 + lane];
        float p1 = pr[h*64 + 32 + lane];
        float ss = p0 * a_src[h*64 + lane] + p1 * a_src[h*64 + 32 + lane];
        float st = p0 * a_tgt[h*64 + lane] + p1 * a_tgt[h*64 + 32 + lane];
#pragma unroll
        for (int off = 16; off; off >>= 1) {
            ss += __shfl_xor_sync(0xffffffffu, ss, off);
            st += __shfl_xor_sync(0xffffffffu, st, off);
        }
        if (lane == 0) {
            g_ssrc[h*N_NODES + gw] = ss;
            g_stgt[h*N_NODES + gw] = st;
        }
    }
}

// ---------------------------------------------------------------------------
// Kernel 3: sparse attention (no adj access). One block per row i.
//   CSR load -> warp-per-head softmax -> float2 gather (thread t owns dims
//   {2t,2t+1}, head = warp id), unroll 8 for MLP, fp32 accumulation.
// ---------------------------------------------------------------------------
__global__ __launch_bounds__(256) void attn_kernel(
    const float* __restrict__ bias,
    float* __restrict__ out)
{
    __shared__ int   nbr[MAXDEG];
    __shared__ float wsm[NHEAD * MAXDEG];
    __shared__ float ssum[NHEAD];

    const int i    = blockIdx.x;
    const int t    = threadIdx.x;
    const int lane = t & 31;
    const int w    = t >> 5;

    const int deg = g_deg[i];
    const int* nrow = g_nbr + (size_t)i * MAXDEG;
    for (int k = t; k < deg; k += 256) nbr[k] = nrow[k];
    __syncthreads();

    // ---- warp-per-head softmax over neighbors -----------------------------
    {
        const int h = w;
        const float ssrc = g_ssrc[h*N_NODES + i];
        const float* stgt = g_stgt + h*N_NODES;
        float* wrow = wsm + h * MAXDEG;

        float lmax = -1e30f;
        for (int k = lane; k < deg; k += 32) {
            float xv = ssrc + stgt[nbr[k]];
            float l  = xv >= 0.f ? xv : 0.2f * xv;    // leaky_relu(0.2)
            wrow[k] = l;
            lmax = fmaxf(lmax, l);
        }
#pragma unroll
        for (int off = 16; off; off >>= 1)
            lmax = fmaxf(lmax, __shfl_xor_sync(0xffffffffu, lmax, off));

        float lsum = 0.f;
        for (int k = lane; k < deg; k += 32) {
            float e = expf(wrow[k] - lmax);
            wrow[k] = e;
            lsum += e;
        }
#pragma unroll
        for (int off = 16; off; off >>= 1)
            lsum += __shfl_xor_sync(0xffffffffu, lsum, off);
        if (lane == 0) ssum[h] = lsum;
    }
    __syncthreads();

    // ---- float2 gather-accumulate, 8-deep MLP -----------------------------
    // thread t owns dims {2t, 2t+1} -> same head (h = t>>5 = w).
    const float* wv = wsm + w * MAXDEG;        // warp-uniform broadcast
    const float2* pbase = reinterpret_cast<const float2*>(g_proj);
    float ax = 0.f, ay = 0.f;
    int k = 0;
    for (; k + 8 <= deg; k += 8) {
        int n0 = nbr[k],   n1 = nbr[k+1], n2 = nbr[k+2], n3 = nbr[k+3];
        int n4 = nbr[k+4], n5 = nbr[k+5], n6 = nbr[k+6], n7 = nbr[k+7];
        float2 f0 = pbase[(size_t)n0 * 256 + t];
        float2 f1 = pbase[(size_t)n1 * 256 + t];
        float2 f2 = pbase[(size_t)n2 * 256 + t];
        float2 f3 = pbase[(size_t)n3 * 256 + t];
        float2 f4 = pbase[(size_t)n4 * 256 + t];
        float2 f5 = pbase[(size_t)n5 * 256 + t];
        float2 f6 = pbase[(size_t)n6 * 256 + t];
        float2 f7 = pbase[(size_t)n7 * 256 + t];
        float w0 = wv[k],   w1 = wv[k+1], w2 = wv[k+2], w3 = wv[k+3];
        float w4 = wv[k+4], w5 = wv[k+5], w6 = wv[k+6], w7 = wv[k+7];
        ax = fmaf(w0, f0.x, ax); ay = fmaf(w0, f0.y, ay);
        ax = fmaf(w1, f1.x, ax); ay = fmaf(w1, f1.y, ay);
        ax = fmaf(w2, f2.x, ax); ay = fmaf(w2, f2.y, ay);
        ax = fmaf(w3, f3.x, ax); ay = fmaf(w3, f3.y, ay);
        ax = fmaf(w4, f4.x, ax); ay = fmaf(w4, f4.y, ay);
        ax = fmaf(w5, f5.x, ax); ay = fmaf(w5, f5.y, ay);
        ax = fmaf(w6, f6.x, ax); ay = fmaf(w6, f6.y, ay);
        ax = fmaf(w7, f7.x, ax); ay = fmaf(w7, f7.y, ay);
    }
    for (; k < deg; k++) {
        float2 f = pbase[(size_t)nbr[k] * 256 + t];
        float wk = wv[k];
        ax = fmaf(wk, f.x, ax); ay = fmaf(wk, f.y, ay);
    }

    const float inv = 1.f / ssum[w];
    float2 sk = *reinterpret_cast<const float2*>(g_skip + (size_t)i*HF + 2*t);
    float2 bz = *reinterpret_cast<const float2*>(bias + 2*t);
    float v0 = ax * inv + sk.x + bz.x;
    float v1 = ay * inv + sk.y + bz.y;
    float2 o;
    o.x = v0 > 0.f ? v0 : expm1f(v0);          // ELU(alpha=1)
    o.y = v1 > 0.f ? v1 : expm1f(v1);
    *reinterpret_cast<float2*>(out + (size_t)i*HF + 2*t) = o;
}

// ---------------------------------------------------------------------------
extern "C" void kernel_launch(void* const* d_in, const int* in_sizes, int n_in,
                              void* d_out, int out_size)
{
    const float* x     = (const float*)d_in[0];
    const float* adj   = (const float*)d_in[1];
    const float* Wp    = (const float*)d_in[2];
    const float* a_src = (const float*)d_in[3];
    const float* a_tgt = (const float*)d_in[4];
    const float* Ws    = (const float*)d_in[5];
    const float* bias  = (const float*)d_in[6];
    float* out = (float*)d_out;

    int write_adj = (out_size >= OUT_ELEMS + ADJ_ELEMS) ? 1 : 0;
    float* out_adj = write_adj ? (out + OUT_ELEMS) : out;

    scan_copy_kernel<<<N_NODES, 256>>>(adj, out_adj, write_adj);
    dim3 ggrid(1024 / BN, N_NODES / BM);          // (8, 32)
    gemm_kernel<<<ggrid, 256>>>(x, Wp, Ws);
    score_kernel<<<N_NODES / 8, 256>>>(a_src, a_tgt);
    attn_kernel<<<N_NODES, 256>>>(bias, out);
}

// round 6
// speedup vs baseline: 1.2808x; 1.0960x over previous
#include <cuda_runtime.h>
#include <cuda_fp16.h>
#include <math.h>

#define N_NODES 4096
#define FIN     128
#define NHEAD   8
#define FOUT    64
#define HF      512                 // NHEAD*FOUT
#define HF2     256                 // half2 per row
#define OUT_ELEMS (N_NODES*HF)      // 2097152
#define ADJ_ELEMS (N_NODES*N_NODES) // 16777216
#define MAXDEG  512

// Scratch (allocation-free rule: __device__ globals)
__device__ float   g_proj[N_NODES*HF];     // fp32 (score path)
__device__ __half2 g_projh2[N_NODES*HF2];  // fp16 copy (gather path), 1KB/row
__device__ float   g_skip[N_NODES*HF];
__device__ float   g_ssrc[NHEAD*N_NODES];
__device__ float   g_stgt[NHEAD*N_NODES];
__device__ int     g_deg[N_NODES];
__device__ int     g_nbr[(size_t)N_NODES*MAXDEG];

// ---------------------------------------------------------------------------
// Kernel 0: adj scan + copy + CSR build. One block per row.
// ---------------------------------------------------------------------------
__global__ __launch_bounds__(256) void scan_copy_kernel(
    const float* __restrict__ adj,
    float* __restrict__ out_adj,
    int write_adj)
{
    __shared__ int warpsum[8];
    const int i    = blockIdx.x;
    const int t    = threadIdx.x;
    const int lane = t & 31;
    const int w    = t >> 5;

    const float4* arow = reinterpret_cast<const float4*>(adj + (size_t)i * N_NODES);
    float4*       orow = reinterpret_cast<float4*>(out_adj + (size_t)i * N_NODES);

    float4 a[4];
#pragma unroll
    for (int v = 0; v < 4; v++) a[v] = arow[4*t + v];
    if (write_adj) {
#pragma unroll
        for (int v = 0; v < 4; v++) orow[4*t + v] = a[v];
    }

    unsigned flags = 0;
#pragma unroll
    for (int v = 0; v < 4; v++) {
        flags |= (a[v].x > -0.5f ? 1u : 0u) << (4*v + 0);
        flags |= (a[v].y > -0.5f ? 1u : 0u) << (4*v + 1);
        flags |= (a[v].z > -0.5f ? 1u : 0u) << (4*v + 2);
        flags |= (a[v].w > -0.5f ? 1u : 0u) << (4*v + 3);
    }
    int c = __popc(flags);

    int incl = c;
#pragma unroll
    for (int off = 1; off < 32; off <<= 1) {
        int n = __shfl_up_sync(0xffffffffu, incl, off);
        if (lane >= off) incl += n;
    }
    if (lane == 31) warpsum[w] = incl;
    __syncthreads();
    int wbase = 0, tot = 0;
#pragma unroll
    for (int ww = 0; ww < 8; ww++) {
        int s = warpsum[ww];
        if (ww < w) wbase += s;
        tot += s;
    }

    int pos = wbase + incl - c;        // exclusive prefix, column-ordered
    int base = 16 * t;
    int* nrow = g_nbr + (size_t)i * MAXDEG;
#pragma unroll
    for (int b = 0; b < 16; b++) {
        if ((flags >> b) & 1u) {
            if (pos < MAXDEG) nrow[pos] = base + b;
            pos++;
        }
    }
    if (t == 0) g_deg[i] = min(tot, MAXDEG);
}

// ---------------------------------------------------------------------------
// Kernel 1: fused projection GEMM. proj tiles also emit an fp16 copy.
// ---------------------------------------------------------------------------
#define BM 128
#define BN 128
#define BK 16

__global__ __launch_bounds__(256, 2) void gemm_kernel(
    const float* __restrict__ x,
    const float* __restrict__ Wp,
    const float* __restrict__ Ws)
{
    __shared__ float xs[BK][BM + 4];
    __shared__ float ws[BK][BN + 4];

    const int bm = blockIdx.y * BM;
    const int bo = blockIdx.x * BN;
    const int t  = threadIdx.x;
    const int tx = t & 15;
    const int ty = t >> 4;

    float acc[8][8];
#pragma unroll
    for (int i = 0; i < 8; i++)
#pragma unroll
        for (int j = 0; j < 8; j++) acc[i][j] = 0.f;

    const float* Wb = (bo < HF) ? (Wp + (size_t)bo * FIN)
                                : (Ws + (size_t)(bo - HF) * FIN);

    for (int kt = 0; kt < FIN; kt += BK) {
#pragma unroll
        for (int v = 0; v < 2; v++) {
            int idx = t + v * 256;
            int row = idx >> 2, f4 = idx & 3;
            float4 xv = *reinterpret_cast<const float4*>(
                x + (size_t)(bm + row) * FIN + kt + f4 * 4);
            xs[f4*4+0][row] = xv.x; xs[f4*4+1][row] = xv.y;
            xs[f4*4+2][row] = xv.z; xs[f4*4+3][row] = xv.w;
        }
#pragma unroll
        for (int v = 0; v < 2; v++) {
            int idx = t + v * 256;
            int o = idx >> 2, f4 = idx & 3;
            float4 wv = *reinterpret_cast<const float4*>(
                Wb + (size_t)o * FIN + kt + f4 * 4);
            ws[f4*4+0][o] = wv.x; ws[f4*4+1][o] = wv.y;
            ws[f4*4+2][o] = wv.z; ws[f4*4+3][o] = wv.w;
        }
        __syncthreads();
#pragma unroll
        for (int k = 0; k < BK; k++) {
            float a[8], b[8];
            *reinterpret_cast<float4*>(a)     = *reinterpret_cast<const float4*>(&xs[k][ty*8]);
            *reinterpret_cast<float4*>(a + 4) = *reinterpret_cast<const float4*>(&xs[k][ty*8+4]);
            *reinterpret_cast<float4*>(b)     = *reinterpret_cast<const float4*>(&ws[k][tx*8]);
            *reinterpret_cast<float4*>(b + 4) = *reinterpret_cast<const float4*>(&ws[k][tx*8+4]);
#pragma unroll
            for (int i = 0; i < 8; i++)
#pragma unroll
                for (int j = 0; j < 8; j++) acc[i][j] = fmaf(a[i], b[j], acc[i][j]);
        }
        __syncthreads();
    }

    if (bo < HF) {
#pragma unroll
        for (int i = 0; i < 8; i++) {
            int m = bm + ty*8 + i;
            float* drow = g_proj + (size_t)m * HF + bo + tx*8;
            *reinterpret_cast<float4*>(drow)     = make_float4(acc[i][0], acc[i][1], acc[i][2], acc[i][3]);
            *reinterpret_cast<float4*>(drow + 4) = make_float4(acc[i][4], acc[i][5], acc[i][6], acc[i][7]);
            __half2* hrow = g_projh2 + (size_t)m * HF2 + (bo >> 1) + tx*4;
            hrow[0] = __floats2half2_rn(acc[i][0], acc[i][1]);
            hrow[1] = __floats2half2_rn(acc[i][2], acc[i][3]);
            hrow[2] = __floats2half2_rn(acc[i][4], acc[i][5]);
            hrow[3] = __floats2half2_rn(acc[i][6], acc[i][7]);
        }
    } else {
        const int cb = bo - HF;
#pragma unroll
        for (int i = 0; i < 8; i++) {
            int m = bm + ty*8 + i;
            float* drow = g_skip + (size_t)m * HF + cb + tx*8;
            *reinterpret_cast<float4*>(drow)     = make_float4(acc[i][0], acc[i][1], acc[i][2], acc[i][3]);
            *reinterpret_cast<float4*>(drow + 4) = make_float4(acc[i][4], acc[i][5], acc[i][6], acc[i][7]);
        }
    }
}

// ---------------------------------------------------------------------------
// Kernel 2: per-node attention scores  s_src[h][n], s_tgt[h][n]
// ---------------------------------------------------------------------------
__global__ __launch_bounds__(256) void score_kernel(
    const float* __restrict__ a_src,
    const float* __restrict__ a_tgt)
{
    int gw   = (blockIdx.x * 256 + threadIdx.x) >> 5;
    int lane = threadIdx.x & 31;
    if (gw >= N_NODES) return;
    const float* pr = g_proj + (size_t)gw * HF;
#pragma unroll
    for (int h = 0; h < NHEAD; h++) {
        float p0 = pr[h*64 + lane];
        float p1 = pr[h*64 + 32 + lane];
        float ss = p0 * a_src[h*64 + lane] + p1 * a_src[h*64 + 32 + lane];
        float st = p0 * a_tgt[h*64 + lane] + p1 * a_tgt[h*64 + 32 + lane];
#pragma unroll
        for (int off = 16; off; off >>= 1) {
            ss += __shfl_xor_sync(0xffffffffu, ss, off);
            st += __shfl_xor_sync(0xffffffffu, st, off);
        }
        if (lane == 0) {
            g_ssrc[h*N_NODES + gw] = ss;
            g_stgt[h*N_NODES + gw] = st;
        }
    }
}

// ---------------------------------------------------------------------------
// Kernel 3: sparse attention. One block per row i.
//   CSR load -> warp-per-head softmax (fp32 scores) -> fp16 half2 gather
//   (thread t owns dims {2t,2t+1}, head = warp id), fp32 accumulation.
// ---------------------------------------------------------------------------
__global__ __launch_bounds__(256) void attn_kernel(
    const float* __restrict__ bias,
    float* __restrict__ out)
{
    __shared__ int   nbr[MAXDEG];
    __shared__ float wsm[NHEAD * MAXDEG];
    __shared__ float ssum[NHEAD];

    const int i    = blockIdx.x;
    const int t    = threadIdx.x;
    const int lane = t & 31;
    const int w    = t >> 5;

    const int deg = g_deg[i];
    const int* nrow = g_nbr + (size_t)i * MAXDEG;
    for (int k = t; k < deg; k += 256) nbr[k] = nrow[k];
    __syncthreads();

    // ---- warp-per-head softmax over neighbors -----------------------------
    {
        const int h = w;
        const float ssrc = g_ssrc[h*N_NODES + i];
        const float* stgt = g_stgt + h*N_NODES;
        float* wrow = wsm + h * MAXDEG;

        float lmax = -1e30f;
        for (int k = lane; k < deg; k += 32) {
            float xv = ssrc + stgt[nbr[k]];
            float l  = xv >= 0.f ? xv : 0.2f * xv;    // leaky_relu(0.2)
            wrow[k] = l;
            lmax = fmaxf(lmax, l);
        }
#pragma unroll
        for (int off = 16; off; off >>= 1)
            lmax = fmaxf(lmax, __shfl_xor_sync(0xffffffffu, lmax, off));

        float lsum = 0.f;
        for (int k = lane; k < deg; k += 32) {
            float e = expf(wrow[k] - lmax);
            wrow[k] = e;
            lsum += e;
        }
#pragma unroll
        for (int off = 16; off; off >>= 1)
            lsum += __shfl_xor_sync(0xffffffffu, lsum, off);
        if (lane == 0) ssum[h] = lsum;
    }
    __syncthreads();

    // ---- fp16 gather-accumulate, 8-deep MLP -------------------------------
    // thread t owns dims {2t, 2t+1}; row stride 1KB -> byte offset n<<10.
    const float* wv = wsm + w * MAXDEG;        // warp-uniform broadcast
    const char* pbt = reinterpret_cast<const char*>(g_projh2) + (size_t)t * 4;
    float ax = 0.f, ay = 0.f;
    int k = 0;
    for (; k + 8 <= deg; k += 8) {
        unsigned o0 = (unsigned)nbr[k]   << 10;
        unsigned o1 = (unsigned)nbr[k+1] << 10;
        unsigned o2 = (unsigned)nbr[k+2] << 10;
        unsigned o3 = (unsigned)nbr[k+3] << 10;
        unsigned o4 = (unsigned)nbr[k+4] << 10;
        unsigned o5 = (unsigned)nbr[k+5] << 10;
        unsigned o6 = (unsigned)nbr[k+6] << 10;
        unsigned o7 = (unsigned)nbr[k+7] << 10;
        __half2 h0 = *reinterpret_cast<const __half2*>(pbt + o0);
        __half2 h1 = *reinterpret_cast<const __half2*>(pbt + o1);
        __half2 h2 = *reinterpret_cast<const __half2*>(pbt + o2);
        __half2 h3 = *reinterpret_cast<const __half2*>(pbt + o3);
        __half2 h4 = *reinterpret_cast<const __half2*>(pbt + o4);
        __half2 h5 = *reinterpret_cast<const __half2*>(pbt + o5);
        __half2 h6 = *reinterpret_cast<const __half2*>(pbt + o6);
        __half2 h7 = *reinterpret_cast<const __half2*>(pbt + o7);
        float w0 = wv[k],   w1 = wv[k+1], w2 = wv[k+2], w3 = wv[k+3];
        float w4 = wv[k+4], w5 = wv[k+5], w6 = wv[k+6], w7 = wv[k+7];
        float2 f0 = __half22float2(h0);
        float2 f1 = __half22float2(h1);
        float2 f2 = __half22float2(h2);
        float2 f3 = __half22float2(h3);
        float2 f4 = __half22float2(h4);
        float2 f5 = __half22float2(h5);
        float2 f6 = __half22float2(h6);
        float2 f7 = __half22float2(h7);
        ax = fmaf(w0, f0.x, ax); ay = fmaf(w0, f0.y, ay);
        ax = fmaf(w1, f1.x, ax); ay = fmaf(w1, f1.y, ay);
        ax = fmaf(w2, f2.x, ax); ay = fmaf(w2, f2.y, ay);
        ax = fmaf(w3, f3.x, ax); ay = fmaf(w3, f3.y, ay);
        ax = fmaf(w4, f4.x, ax); ay = fmaf(w4, f4.y, ay);
        ax = fmaf(w5, f5.x, ax); ay = fmaf(w5, f5.y, ay);
        ax = fmaf(w6, f6.x, ax); ay = fmaf(w6, f6.y, ay);
        ax = fmaf(w7, f7.x, ax); ay = fmaf(w7, f7.y, ay);
    }
    for (; k < deg; k++) {
        unsigned o = (unsigned)nbr[k] << 10;
        float2 f = __half22float2(*reinterpret_cast<const __half2*>(pbt + o));
        float wk = wv[k];
        ax = fmaf(wk, f.x, ax); ay = fmaf(wk, f.y, ay);
    }

    const float inv = 1.f / ssum[w];
    float2 sk = *reinterpret_cast<const float2*>(g_skip + (size_t)i*HF + 2*t);
    float2 bz = *reinterpret_cast<const float2*>(bias + 2*t);
    float v0 = ax * inv + sk.x + bz.x;
    float v1 = ay * inv + sk.y + bz.y;
    float2 o;
    o.x = v0 > 0.f ? v0 : expm1f(v0);          // ELU(alpha=1)
    o.y = v1 > 0.f ? v1 : expm1f(v1);
    *reinterpret_cast<float2*>(out + (size_t)i*HF + 2*t) = o;
}

// ---------------------------------------------------------------------------
extern "C" void kernel_launch(void* const* d_in, const int* in_sizes, int n_in,
                              void* d_out, int out_size)
{
    const float* x     = (const float*)d_in[0];
    const float* adj   = (const float*)d_in[1];
    const float* Wp    = (const float*)d_in[2];
    const float* a_src = (const float*)d_in[3];
    const float* a_tgt = (const float*)d_in[4];
    const float* Ws    = (const float*)d_in[5];
    const float* bias  = (const float*)d_in[6];
    float* out = (float*)d_out;

    int write_adj = (out_size >= OUT_ELEMS + ADJ_ELEMS) ? 1 : 0;
    float* out_adj = write_adj ? (out + OUT_ELEMS) : out;

    scan_copy_kernel<<<N_NODES, 256>>>(adj, out_adj, write_adj);
    dim3 ggrid(1024 / BN, N_NODES / BM);          // (8, 32)
    gemm_kernel<<<ggrid, 256>>>(x, Wp, Ws);
    score_kernel<<<N_NODES / 8, 256>>>(a_src, a_tgt);
    attn_kernel<<<N_NODES, 256>>>(bias, out);
}